// round 16
// baseline (speedup 1.0000x reference)
#include <cuda_runtime.h>
#include <cuda_fp16.h>
#include <cstdint>

#define BB 2
#define SS 2048
#define DD 512
#define HH 8
#define DKK 64

// Scratch (static device globals: allocation-free per harness rules)
__device__ __half g_h16[3*BB*HH*SS*DKK];   // fp16 per-head Q,K,V: [z][b][h][s][64]
__device__ __half g_inh[3*BB*SS*DD];       // fp16 activations [z][b*s][512]
__device__ __half g_Hc16[BB*SS*DD];        // fp16 attention output [b*s][512]
__device__ __half g_Wh[4*DD*DD];           // fp16 weights [WQ;WK;WV;WO], [n][k]
__device__ float  g_bqkv[3*DD];
__device__ int    g_len[2*BB];             // [rowlen[b], collen[b]]

// ---------------------------------------------------------------------------
// helpers (base-target PTX: sm_80-era mma.sync + cp.async + ldmatrix)
// ---------------------------------------------------------------------------
__device__ __forceinline__ uint32_t pack_f16x2(float lo, float hi) {
    uint32_t r;
    asm("cvt.rn.f16x2.f32 %0, %1, %2;" : "=r"(r) : "f"(hi), "f"(lo));
    return r;
}
__device__ __forceinline__ void mma_f16(float* c, const uint32_t* a, uint32_t b0, uint32_t b1) {
    asm volatile("mma.sync.aligned.m16n8k16.row.col.f32.f16.f16.f32 "
        "{%0,%1,%2,%3}, {%4,%5,%6,%7}, {%8,%9}, {%0,%1,%2,%3};"
        : "+f"(c[0]), "+f"(c[1]), "+f"(c[2]), "+f"(c[3])
        : "r"(a[0]), "r"(a[1]), "r"(a[2]), "r"(a[3]), "r"(b0), "r"(b1));
}
__device__ __forceinline__ void ldm_x4(uint32_t& r0, uint32_t& r1, uint32_t& r2, uint32_t& r3,
                                       uint32_t addr) {
    asm volatile("ldmatrix.sync.aligned.m8n8.x4.shared.b16 {%0,%1,%2,%3}, [%4];"
        : "=r"(r0), "=r"(r1), "=r"(r2), "=r"(r3) : "r"(addr));
}
__device__ __forceinline__ void ldm_x4_t(uint32_t& r0, uint32_t& r1, uint32_t& r2, uint32_t& r3,
                                         uint32_t addr) {
    asm volatile("ldmatrix.sync.aligned.m8n8.x4.trans.shared.b16 {%0,%1,%2,%3}, [%4];"
        : "=r"(r0), "=r"(r1), "=r"(r2), "=r"(r3) : "r"(addr));
}
__device__ __forceinline__ uint32_t smem_u32(const void* p) {
    uint32_t a;
    asm("{ .reg .u64 t; cvta.to.shared.u64 t, %1; cvt.u32.u64 %0, t; }" : "=r"(a) : "l"(p));
    return a;
}
__device__ __forceinline__ void cpa16(uint32_t dst, const void* src) {
    asm volatile("cp.async.cg.shared.global [%0], [%1], 16;" :: "r"(dst), "l"(src));
}
__device__ __forceinline__ void cpa_commit() { asm volatile("cp.async.commit_group;"); }

// ---------------------------------------------------------------------------
// Prep: mask lengths + bias concat + fp16 conversion
// ---------------------------------------------------------------------------
__global__ void prep_kernel(const int* __restrict__ rm, const int* __restrict__ cm,
                            const float* __restrict__ WQ, const float* __restrict__ WK,
                            const float* __restrict__ WV, const float* __restrict__ WO,
                            const float* __restrict__ bQ, const float* __restrict__ bK,
                            const float* __restrict__ bV,
                            const float* __restrict__ inQ, const float* __restrict__ inK,
                            const float* __restrict__ inV) {
    int blk = blockIdx.x, t = threadIdx.x;
    if (blk < 2) {
        __shared__ int sr[256], sc[256];
        int b = blk, r = 0, c = 0;
        for (int s = t; s < SS; s += 256) { r += rm[b*SS + s]; c += cm[b*SS + s]; }
        sr[t] = r; sc[t] = c;
        __syncthreads();
        for (int o = 128; o > 0; o >>= 1) {
            if (t < o) { sr[t] += sr[t+o]; sc[t] += sc[t+o]; }
            __syncthreads();
        }
        if (t == 0) { g_len[b] = sr[0]; g_len[BB + b] = sc[0]; }
        if (blk == 0)
            for (int i = t; i < DD; i += 256) {
                g_bqkv[i] = bQ[i]; g_bqkv[DD + i] = bK[i]; g_bqkv[2*DD + i] = bV[i];
            }
        return;
    }
    if (blk < 66) {
        int base = (blk - 2) * 4096 + t;
        const float* srcs[4] = { WQ, WK, WV, WO };
#pragma unroll
        for (int i = 0; i < 16; i++) {
            int f4 = base + i * 256;
            int mat = f4 >> 16;
            int off = (f4 & 65535) << 2;
            float4 v = *(const float4*)(srcs[mat] + off);
            uint2 u = { pack_f16x2(v.x, v.y), pack_f16x2(v.z, v.w) };
            *(uint2*)(g_Wh + (size_t)mat*DD*DD + off) = u;
        }
        return;
    }
    int base = (blk - 66) * 256 + t;
#pragma unroll
    for (int i = 0; i < 24; i++) {
        int f4 = base + i * 65536;
        int tsr = f4 / 524288;
        int off = (f4 - tsr * 524288) << 2;
        const float* s = (tsr == 0) ? inQ : (tsr == 1) ? inK : inV;
        float4 v = *(const float4*)(s + off);
        uint2 u = { pack_f16x2(v.x, v.y), pack_f16x2(v.z, v.w) };
        *(uint2*)(g_inh + (size_t)tsr*BB*SS*DD + off) = u;
    }
}

// ---------------------------------------------------------------------------
// fp16 GEMM v1 (qkv): K-chunk 32, 4-stage, BM=64 BN=128. [R13 measured winner]
// ---------------------------------------------------------------------------
#define GSTR 40

template<int BM, int BN, int EPI>
__device__ __forceinline__ void gemm_f16(const __half* __restrict__ Ag,
                                         const __half* __restrict__ Wg,
                                         const float* __restrict__ bg,
                                         float* __restrict__ Cg,
                                         int bm, int bn_local, int z) {
    extern __shared__ __half sh[];
    constexpr int SS_A  = BM * GSTR;
    constexpr int SS_B  = BN * GSTR;
    constexpr int SS_AB = SS_A + SS_B;
    constexpr int NWM = 8 / (BN / 32);
    constexpr int TM  = BM / (NWM * 16);
    float* bias_s = (float*)(sh + 4 * SS_AB);
    const uint32_t sb = smem_u32(sh);
    const int tid = threadIdx.x;
    const int wid = tid >> 5, lane = tid & 31, gid = lane >> 2, tig = lane & 3;
    const int warp_m = wid % NWM, warp_n = wid / NWM;
    const int lrow = lane & 15, lcol = (lane >> 4) << 3;

    if (tid < BN) bias_s[tid] = bg[tid];

    float acc[TM][4][4];
#pragma unroll
    for (int a = 0; a < TM; a++)
#pragma unroll
        for (int b = 0; b < 4; b++)
#pragma unroll
            for (int k = 0; k < 4; k++) acc[a][b][k] = 0.f;

    const int r0 = tid >> 2, c0 = (tid & 3) << 3;
    const __half* pA = Ag + (size_t)(bm + r0) * DD + c0;
    const __half* pB = Wg + (size_t)(bn_local + r0) * DD + c0;

#define G_LOAD(cc, buf) do { \
    _Pragma("unroll") \
    for (int i = 0; i < BM/64; i++) \
        cpa16(sb + (uint32_t)((buf)*SS_AB + (i*64 + r0)*GSTR + c0)*2, \
              pA + (size_t)i*64*DD + (cc)*32); \
    _Pragma("unroll") \
    for (int i = 0; i < BN/64; i++) \
        cpa16(sb + (uint32_t)((buf)*SS_AB + SS_A + (i*64 + r0)*GSTR + c0)*2, \
              pB + (size_t)i*64*DD + (cc)*32); \
    cpa_commit(); \
} while (0)

    G_LOAD(0, 0); G_LOAD(1, 1); G_LOAD(2, 2);

    for (int c = 0; c < 16; c++) {
        asm volatile("cp.async.wait_group 2;");
        __syncthreads();
        if (c + 3 < 16) G_LOAD(c + 3, (c + 3) & 3); else cpa_commit();

        const uint32_t abase = sb + (uint32_t)((c & 3) * SS_AB) * 2;
        const uint32_t bbase = abase + (uint32_t)SS_A * 2;
#pragma unroll
        for (int ks = 0; ks < 2; ks++) {
            uint32_t af[TM][4];
#pragma unroll
            for (int mt = 0; mt < TM; mt++)
                ldm_x4(af[mt][0], af[mt][1], af[mt][2], af[mt][3],
                       abase + (uint32_t)((warp_m*(BM/NWM) + mt*16 + lrow)*GSTR + ks*16 + lcol)*2);
#pragma unroll
            for (int ns = 0; ns < 2; ns++) {
                uint32_t b0, b1, b2, b3;
                ldm_x4(b0, b1, b2, b3,
                       bbase + (uint32_t)((warp_n*32 + ns*16 + lrow)*GSTR + ks*16 + lcol)*2);
#pragma unroll
                for (int mt = 0; mt < TM; mt++) {
                    mma_f16(acc[mt][ns*2],   af[mt], b0, b2);
                    mma_f16(acc[mt][ns*2+1], af[mt], b1, b3);
                }
            }
        }
    }
#undef G_LOAD

#pragma unroll
    for (int mt = 0; mt < TM; mt++) {
        int rg = bm + warp_m*(BM/NWM) + mt*16 + gid;
#pragma unroll
        for (int tn = 0; tn < 4; tn++) {
            int cc = warp_n*32 + tn*8 + tig*2;
            float b0 = bias_s[cc], b1 = bias_s[cc+1];
            if (EPI == 0) {
                *(float2*)(Cg + (size_t)rg*DD + bn_local + cc) =
                    make_float2(acc[mt][tn][0] + b0, acc[mt][tn][1] + b1);
                *(float2*)(Cg + (size_t)(rg+8)*DD + bn_local + cc) =
                    make_float2(acc[mt][tn][2] + b0, acc[mt][tn][3] + b1);
            } else {
                int col = bn_local + cc;
                int h = col >> 6, d = col & 63;
#pragma unroll
                for (int rr = 0; rr < 2; rr++) {
                    int rgl = rg + rr*8;
                    int b = rgl >> 11, s = rgl & 2047;
                    uint32_t hv = pack_f16x2(acc[mt][tn][rr*2+0] + b0,
                                             acc[mt][tn][rr*2+1] + b1);
                    *(uint32_t*)(g_h16 + ((((size_t)z*BB + b)*HH + h)*SS + s)*DKK + d) = hv;
                }
            }
        }
    }
}

#define GEMM_SMEM_QKV (4*((64 + 128)*GSTR)*2 + 512)

__global__ void __launch_bounds__(256, 3) qkv_tc_kernel() {
    int bm = blockIdx.x * 64;
    int b = bm >> 11, s_start = bm & 2047;
    int need = max(g_len[b], g_len[BB + b]);
    need = (need + 63) & ~63;
    if (s_start >= need) return;
    int bn = blockIdx.y * 128;
    int z = bn >> 9;
    gemm_f16<64, 128, 1>(g_inh + (size_t)z*BB*SS*DD, g_Wh + (size_t)z*DD*DD,
                         g_bqkv + bn, nullptr, bm, bn & 511, z);
}

// ---------------------------------------------------------------------------
// fp16 GEMM v2 (oproj): K-chunk 64, 3-stage, BM=64 BN=128. [R15 measured]
// ---------------------------------------------------------------------------
#define OSTR 72
#define OPROJ_STAGE ((64 + 128) * OSTR)
#define GEMM_SMEM_OPROJ (3 * OPROJ_STAGE * 2 + 512)

__global__ void __launch_bounds__(256, 2) oproj_tc_kernel(const float* __restrict__ bO,
                                                          float* __restrict__ out) {
    int bm = blockIdx.x * 64;
    int b = bm >> 11, s_start = bm & 2047;
    int rl = g_len[b];
    int bn = blockIdx.y * 128;
    const float* bg = bO + bn;
    if (s_start >= rl) {
#pragma unroll
        for (int i = 0; i < 8; i++) {
            int idx = threadIdx.x + i*256;
            int r = idx >> 5, cf = (idx & 31) << 2;
            float4 bv = *(const float4*)(bg + cf);
            *(float4*)(out + (size_t)(bm + r)*DD + bn + cf) = bv;
        }
        return;
    }

    extern __shared__ __half sh[];
    constexpr int SS_A = 64 * OSTR;
    float* bias_s = (float*)(sh + 3 * OPROJ_STAGE);
    const uint32_t sb = smem_u32(sh);
    const int tid = threadIdx.x;
    const int wid = tid >> 5, lane = tid & 31, gid = lane >> 2, tig = lane & 3;
    const int warp_m = wid & 1, warp_n = wid >> 1;
    const int lrow = lane & 15, lcol = (lane >> 4) << 3;

    if (tid < 128) bias_s[tid] = bg[tid];

    float acc[2][4][4];
#pragma unroll
    for (int a = 0; a < 2; a++)
#pragma unroll
        for (int bq = 0; bq < 4; bq++)
#pragma unroll
            for (int k = 0; k < 4; k++) acc[a][bq][k] = 0.f;

    const int r0 = tid >> 3, c0 = (tid & 7) << 3;
    const __half* pA = g_Hc16 + (size_t)(bm + r0) * DD + c0;
    const __half* pB = g_Wh + 3*(size_t)DD*DD + (size_t)(bn + r0) * DD + c0;

#define O_LOAD(cc, buf) do { \
    _Pragma("unroll") \
    for (int i = 0; i < 2; i++) \
        cpa16(sb + (uint32_t)((buf)*OPROJ_STAGE + (i*32 + r0)*OSTR + c0)*2, \
              pA + (size_t)i*32*DD + (cc)*64); \
    _Pragma("unroll") \
    for (int i = 0; i < 4; i++) \
        cpa16(sb + (uint32_t)((buf)*OPROJ_STAGE + SS_A + (i*32 + r0)*OSTR + c0)*2, \
              pB + (size_t)i*32*DD + (cc)*64); \
    cpa_commit(); \
} while (0)

    O_LOAD(0, 0); O_LOAD(1, 1);

    for (int c = 0; c < 8; c++) {
        asm volatile("cp.async.wait_group 1;");
        __syncthreads();
        if (c + 2 < 8) O_LOAD(c + 2, (c + 2) % 3); else cpa_commit();

        const uint32_t abase = sb + (uint32_t)((c % 3) * OPROJ_STAGE) * 2;
        const uint32_t bbase = abase + (uint32_t)SS_A * 2;
#pragma unroll
        for (int ks = 0; ks < 4; ks++) {
            uint32_t af[2][4];
#pragma unroll
            for (int mt = 0; mt < 2; mt++)
                ldm_x4(af[mt][0], af[mt][1], af[mt][2], af[mt][3],
                       abase + (uint32_t)((warp_m*32 + mt*16 + lrow)*OSTR + ks*16 + lcol)*2);
#pragma unroll
            for (int ns = 0; ns < 2; ns++) {
                uint32_t b0, b1, b2, b3;
                ldm_x4(b0, b1, b2, b3,
                       bbase + (uint32_t)((warp_n*32 + ns*16 + lrow)*OSTR + ks*16 + lcol)*2);
#pragma unroll
                for (int mt = 0; mt < 2; mt++) {
                    mma_f16(acc[mt][ns*2],   af[mt], b0, b2);
                    mma_f16(acc[mt][ns*2+1], af[mt], b1, b3);
                }
            }
        }
    }
#undef O_LOAD

#pragma unroll
    for (int mt = 0; mt < 2; mt++) {
        int rg = bm + warp_m*32 + mt*16 + gid;
#pragma unroll
        for (int tn = 0; tn < 4; tn++) {
            int cc = warp_n*32 + tn*8 + tig*2;
            float b0 = bias_s[cc], b1 = bias_s[cc+1];
            *(float2*)(out + (size_t)rg*DD + bn + cc) =
                make_float2(acc[mt][tn][0] + b0, acc[mt][tn][1] + b1);
            *(float2*)(out + (size_t)(rg+8)*DD + bn + cc) =
                make_float2(acc[mt][tn][2] + b0, acc[mt][tn][3] + b1);
        }
    }
}

// ---------------------------------------------------------------------------
// Flash attention (fp16 fragments), Br=64 x Bc=128, 128 threads (4 warps).
// Warp-uniform causal fine-grained skip: 16-col K-chunks entirely above the
// causal boundary (or >= collen) are skipped in QK, softmax, and PV.
// Skipped chunks contributed exactly 0 / -1e30-losers -> bit-identical output.
// smem halfs (stride 72): Q[64][72]@0  K[2][128][72]@4608  V[2][128][72]@23040
// ---------------------------------------------------------------------------
#define HSTR 72
#define AQ 0
#define AK 4608
#define AV 23040
#define ATTN_SMEM (41472*2)

__global__ void __launch_bounds__(128, 2) attn_kernel() {
    extern __shared__ __half sah[];
    const uint32_t sb = smem_u32(sah);

    const int bh = blockIdx.z;
    const int b = bh >> 3, h = bh & 7;
    const int qt = 31 - (int)blockIdx.y;      // heavy tiles first
    const int qbase = qt << 6;
    const int rowlen = g_len[b], collen = g_len[BB + b];
    const int tid = threadIdx.x, wid = tid >> 5, lane = tid & 31;
    const int gid = lane >> 2, tig = lane & 3;
    __half* Hp = g_Hc16 + (size_t)b*SS*DD + h*DKK;

    if (qbase >= rowlen || collen <= 0) return;   // oproj bias path covers these rows

    const __half* Qp = g_h16 + ((0*(size_t)BB + b)*HH + h)*(size_t)SS*DKK;
    const __half* Kp = g_h16 + ((1*(size_t)BB + b)*HH + h)*(size_t)SS*DKK;
    const __half* Vp = g_h16 + ((2*(size_t)BB + b)*HH + h)*(size_t)SS*DKK;

    const int kmax = min(qbase + 64, collen);
    const int nk = (kmax + 127) >> 7;          // 128-wide k-tiles

#pragma unroll
    for (int i = 0; i < 4; i++) {
        int e = tid + i*128, r = e >> 3, c8 = (e & 7) << 3;
        cpa16(sb + (uint32_t)(AQ + r*HSTR + c8)*2, Qp + (size_t)(qbase + r)*DKK + c8);
    }
#define KV_LOAD(kb, s) do { \
    _Pragma("unroll") \
    for (int i = 0; i < 8; i++) { \
        int e = tid + i*128, r = e >> 3, c8 = (e & 7) << 3; \
        cpa16(sb + (uint32_t)(AK + (s)*9216 + r*HSTR + c8)*2, Kp + (size_t)((kb) + r)*DKK + c8); \
        cpa16(sb + (uint32_t)(AV + (s)*9216 + r*HSTR + c8)*2, Vp + (size_t)((kb) + r)*DKK + c8); \
    } \
} while (0)
    KV_LOAD(0, 0); cpa_commit();

    const int wr = wid * 16;
    const int q0 = qbase + wr + gid, q1 = q0 + 8;
    const int q1max_w = qbase + wr + 15;                  // warp's highest row
    const int kcap = min(q1max_w, collen - 1);            // last useful k-col
    float m0 = -1e30f, m1 = -1e30f, l0 = 0.f, l1 = 0.f;
    float oacc[8][4];
#pragma unroll
    for (int nt = 0; nt < 8; nt++)
#pragma unroll
        for (int i = 0; i < 4; i++) oacc[nt][i] = 0.f;

    uint32_t qf[4][4];
    const int lrow = lane & 15, lcol = (lane >> 4) << 3;

    for (int kt = 0; kt < nk; kt++) {
        const int kbase = kt << 7;
        const int buf = kt & 1;
        asm volatile("cp.async.wait_group 0;");
        __syncthreads();
        if (kt == 0) {
#pragma unroll
            for (int ks = 0; ks < 4; ks++)
                ldm_x4(qf[ks][0], qf[ks][1], qf[ks][2], qf[ks][3],
                       sb + (uint32_t)(AQ + (wr + lrow)*HSTR + ks*16 + lcol)*2);
        }
        if (kt + 1 < nk) { KV_LOAD(kbase + 128, buf ^ 1); cpa_commit(); }

        const uint32_t kbuf = sb + (uint32_t)(AK + buf*9216)*2;
        const uint32_t vbuf = sb + (uint32_t)(AV + buf*9216)*2;

        // warp-uniform chunk bound: chunks nb with kbase+16*nb > kcap are
        // entirely masked for every row this warp owns -> skip everywhere.
        int hic = (kcap - kbase) >> 4;                    // >= 0 guaranteed
        if (hic > 7) hic = 7;
        const int nhi = 2*hic + 1;

        float sacc[16][4];
#pragma unroll
        for (int nt = 0; nt < 16; nt++)
#pragma unroll
            for (int i = 0; i < 4; i++) sacc[nt][i] = 0.f;
#pragma unroll
        for (int ks = 0; ks < 4; ks++) {
#pragma unroll
            for (int nb = 0; nb < 8; nb++) {
                if (nb > hic) break;
                uint32_t r0, r1, r2, r3;
                ldm_x4(r0, r1, r2, r3,
                       kbuf + (uint32_t)((nb*16 + lrow)*HSTR + ks*16 + lcol)*2);
                mma_f16(sacc[nb*2],   qf[ks], r0, r2);
                mma_f16(sacc[nb*2+1], qf[ks], r1, r3);
            }
        }

#pragma unroll
        for (int nt = 0; nt < 16; nt++) {
            if (nt > nhi) break;
            const int kc = kbase + nt*8 + tig*2;
            sacc[nt][0] = (kc   <= q0 && q0 < rowlen && kc   < collen) ? sacc[nt][0]*0.125f : -1e30f;
            sacc[nt][1] = (kc+1 <= q0 && q0 < rowlen && kc+1 < collen) ? sacc[nt][1]*0.125f : -1e30f;
            sacc[nt][2] = (kc   <= q1 && q1 < rowlen && kc   < collen) ? sacc[nt][2]*0.125f : -1e30f;
            sacc[nt][3] = (kc+1 <= q1 && q1 < rowlen && kc+1 < collen) ? sacc[nt][3]*0.125f : -1e30f;
        }

        float a0 = -1e30f, a1 = -1e30f;
#pragma unroll
        for (int nt = 0; nt < 16; nt++) {
            if (nt > nhi) break;
            a0 = fmaxf(a0, fmaxf(sacc[nt][0], sacc[nt][1]));
            a1 = fmaxf(a1, fmaxf(sacc[nt][2], sacc[nt][3]));
        }
        a0 = fmaxf(a0, __shfl_xor_sync(0xffffffffu, a0, 1));
        a0 = fmaxf(a0, __shfl_xor_sync(0xffffffffu, a0, 2));
        a1 = fmaxf(a1, __shfl_xor_sync(0xffffffffu, a1, 1));
        a1 = fmaxf(a1, __shfl_xor_sync(0xffffffffu, a1, 2));

        const float mn0 = fmaxf(m0, a0), mn1 = fmaxf(m1, a1);
        const float sc0 = __expf(m0 - mn0), sc1 = __expf(m1 - mn1);
        l0 *= sc0; l1 *= sc1; m0 = mn0; m1 = mn1;
#pragma unroll
        for (int nt = 0; nt < 8; nt++) {
            oacc[nt][0] *= sc0; oacc[nt][1] *= sc0;
            oacc[nt][2] *= sc1; oacc[nt][3] *= sc1;
        }

        float rs0 = 0.f, rs1 = 0.f;
#pragma unroll
        for (int nt = 0; nt < 16; nt++) {
            if (nt > nhi) break;
            sacc[nt][0] = __expf(sacc[nt][0] - mn0);
            sacc[nt][1] = __expf(sacc[nt][1] - mn0);
            sacc[nt][2] = __expf(sacc[nt][2] - mn1);
            sacc[nt][3] = __expf(sacc[nt][3] - mn1);
            rs0 += sacc[nt][0] + sacc[nt][1];
            rs1 += sacc[nt][2] + sacc[nt][3];
        }
        rs0 += __shfl_xor_sync(0xffffffffu, rs0, 1);
        rs0 += __shfl_xor_sync(0xffffffffu, rs0, 2);
        rs1 += __shfl_xor_sync(0xffffffffu, rs1, 1);
        rs1 += __shfl_xor_sync(0xffffffffu, rs1, 2);
        l0 += rs0; l1 += rs1;

#pragma unroll
        for (int ks = 0; ks < 8; ks++) {
            if (ks > hic) break;
            uint32_t pa[4];
            pa[0] = pack_f16x2(sacc[2*ks][0],   sacc[2*ks][1]);
            pa[1] = pack_f16x2(sacc[2*ks][2],   sacc[2*ks][3]);
            pa[2] = pack_f16x2(sacc[2*ks+1][0], sacc[2*ks+1][1]);
            pa[3] = pack_f16x2(sacc[2*ks+1][2], sacc[2*ks+1][3]);
#pragma unroll
            for (int db = 0; db < 4; db++) {
                uint32_t v0, v1, v2, v3;
                ldm_x4_t(v0, v1, v2, v3,
                         vbuf + (uint32_t)((ks*16 + lrow)*HSTR + db*16 + lcol)*2);
                mma_f16(oacc[db*2],   pa, v0, v1);
                mma_f16(oacc[db*2+1], pa, v2, v3);
            }
        }
    }
#undef KV_LOAD

    const float inv0 = (q0 < rowlen && l0 > 0.f) ? 1.f / l0 : 0.f;
    const float inv1 = (q1 < rowlen && l1 > 0.f) ? 1.f / l1 : 0.f;
#pragma unroll
    for (int nt = 0; nt < 8; nt++) {
        const int cc = nt*8 + tig*2;
        *(uint32_t*)(Hp + (size_t)q0*DD + cc) = pack_f16x2(oacc[nt][0]*inv0, oacc[nt][1]*inv0);
        *(uint32_t*)(Hp + (size_t)q1*DD + cc) = pack_f16x2(oacc[nt][2]*inv1, oacc[nt][3]*inv1);
    }
}

// ---------------------------------------------------------------------------
extern "C" void kernel_launch(void* const* d_in, const int* in_sizes, int n_in,
                              void* d_out, int out_size) {
    const float* in_Q = (const float*)d_in[0];
    const float* in_K = (const float*)d_in[1];
    const float* in_V = (const float*)d_in[2];
    const int*   rm   = (const int*)d_in[3];
    const int*   cm   = (const int*)d_in[4];
    const float* WQ = (const float*)d_in[5];  const float* bQ = (const float*)d_in[6];
    const float* WK = (const float*)d_in[7];  const float* bK = (const float*)d_in[8];
    const float* WV = (const float*)d_in[9];  const float* bV = (const float*)d_in[10];
    const float* WO = (const float*)d_in[11]; const float* bO = (const float*)d_in[12];
    float* out = (float*)d_out;

    cudaFuncSetAttribute(qkv_tc_kernel,   cudaFuncAttributeMaxDynamicSharedMemorySize, GEMM_SMEM_QKV);
    cudaFuncSetAttribute(oproj_tc_kernel, cudaFuncAttributeMaxDynamicSharedMemorySize, GEMM_SMEM_OPROJ);
    cudaFuncSetAttribute(attn_kernel,     cudaFuncAttributeMaxDynamicSharedMemorySize, ATTN_SMEM);

    prep_kernel<<<322, 256>>>(rm, cm, WQ, WK, WV, WO, bQ, bK, bV, in_Q, in_K, in_V);

    dim3 g1(64, 12);                   // M=4096/64, N=1536/128
    qkv_tc_kernel<<<g1, 256, GEMM_SMEM_QKV>>>();

    dim3 g2(1, 32, 16);                // 64-row q-tiles x (b*h), heavy-first
    attn_kernel<<<g2, 128, ATTN_SMEM>>>();

    dim3 g3(64, 4);                    // M=4096/64, N=512/128
    oproj_tc_kernel<<<g3, 256, GEMM_SMEM_OPROJ>>>(bO, out);
}

// round 17
// speedup vs baseline: 1.1299x; 1.1299x over previous
#include <cuda_runtime.h>
#include <cuda_fp16.h>
#include <cstdint>

#define BB 2
#define SS 2048
#define DD 512
#define HH 8
#define DKK 64

// Scratch (static device globals: allocation-free per harness rules)
__device__ __half g_h16[3*BB*HH*SS*DKK];   // fp16 per-head Q,K,V: [z][b][h][s][64]
__device__ __half g_inh[3*BB*SS*DD];       // fp16 activations [z][b*s][512]
__device__ __half g_Hc16[BB*SS*DD];        // fp16 attention output [b*s][512]
__device__ __half g_Wh[4*DD*DD];           // fp16 weights [WQ;WK;WV;WO], [n][k]
__device__ float  g_bqkv[3*DD];
__device__ int    g_len[2*BB];             // [rowlen[b], collen[b]]

// ---------------------------------------------------------------------------
// helpers (base-target PTX: sm_80-era mma.sync + cp.async + ldmatrix)
// ---------------------------------------------------------------------------
__device__ __forceinline__ uint32_t pack_f16x2(float lo, float hi) {
    uint32_t r;
    asm("cvt.rn.f16x2.f32 %0, %1, %2;" : "=r"(r) : "f"(hi), "f"(lo));
    return r;
}
__device__ __forceinline__ void mma_f16(float* c, const uint32_t* a, uint32_t b0, uint32_t b1) {
    asm volatile("mma.sync.aligned.m16n8k16.row.col.f32.f16.f16.f32 "
        "{%0,%1,%2,%3}, {%4,%5,%6,%7}, {%8,%9}, {%0,%1,%2,%3};"
        : "+f"(c[0]), "+f"(c[1]), "+f"(c[2]), "+f"(c[3])
        : "r"(a[0]), "r"(a[1]), "r"(a[2]), "r"(a[3]), "r"(b0), "r"(b1));
}
__device__ __forceinline__ void ldm_x4(uint32_t& r0, uint32_t& r1, uint32_t& r2, uint32_t& r3,
                                       uint32_t addr) {
    asm volatile("ldmatrix.sync.aligned.m8n8.x4.shared.b16 {%0,%1,%2,%3}, [%4];"
        : "=r"(r0), "=r"(r1), "=r"(r2), "=r"(r3) : "r"(addr));
}
__device__ __forceinline__ void ldm_x4_t(uint32_t& r0, uint32_t& r1, uint32_t& r2, uint32_t& r3,
                                         uint32_t addr) {
    asm volatile("ldmatrix.sync.aligned.m8n8.x4.trans.shared.b16 {%0,%1,%2,%3}, [%4];"
        : "=r"(r0), "=r"(r1), "=r"(r2), "=r"(r3) : "r"(addr));
}
__device__ __forceinline__ uint32_t smem_u32(const void* p) {
    uint32_t a;
    asm("{ .reg .u64 t; cvta.to.shared.u64 t, %1; cvt.u32.u64 %0, t; }" : "=r"(a) : "l"(p));
    return a;
}
__device__ __forceinline__ void cpa16(uint32_t dst, const void* src) {
    asm volatile("cp.async.cg.shared.global [%0], [%1], 16;" :: "r"(dst), "l"(src));
}
__device__ __forceinline__ void cpa_commit() { asm volatile("cp.async.commit_group;"); }

// ---------------------------------------------------------------------------
// Prep: mask lengths + bias concat + fp16 conversion
// ---------------------------------------------------------------------------
__global__ void prep_kernel(const int* __restrict__ rm, const int* __restrict__ cm,
                            const float* __restrict__ WQ, const float* __restrict__ WK,
                            const float* __restrict__ WV, const float* __restrict__ WO,
                            const float* __restrict__ bQ, const float* __restrict__ bK,
                            const float* __restrict__ bV,
                            const float* __restrict__ inQ, const float* __restrict__ inK,
                            const float* __restrict__ inV) {
    int blk = blockIdx.x, t = threadIdx.x;
    if (blk < 2) {
        __shared__ int sr[256], sc[256];
        int b = blk, r = 0, c = 0;
        for (int s = t; s < SS; s += 256) { r += rm[b*SS + s]; c += cm[b*SS + s]; }
        sr[t] = r; sc[t] = c;
        __syncthreads();
        for (int o = 128; o > 0; o >>= 1) {
            if (t < o) { sr[t] += sr[t+o]; sc[t] += sc[t+o]; }
            __syncthreads();
        }
        if (t == 0) { g_len[b] = sr[0]; g_len[BB + b] = sc[0]; }
        if (blk == 0)
            for (int i = t; i < DD; i += 256) {
                g_bqkv[i] = bQ[i]; g_bqkv[DD + i] = bK[i]; g_bqkv[2*DD + i] = bV[i];
            }
        return;
    }
    if (blk < 66) {
        int base = (blk - 2) * 4096 + t;
        const float* srcs[4] = { WQ, WK, WV, WO };
#pragma unroll
        for (int i = 0; i < 16; i++) {
            int f4 = base + i * 256;
            int mat = f4 >> 16;
            int off = (f4 & 65535) << 2;
            float4 v = *(const float4*)(srcs[mat] + off);
            uint2 u = { pack_f16x2(v.x, v.y), pack_f16x2(v.z, v.w) };
            *(uint2*)(g_Wh + (size_t)mat*DD*DD + off) = u;
        }
        return;
    }
    int base = (blk - 66) * 256 + t;
#pragma unroll
    for (int i = 0; i < 24; i++) {
        int f4 = base + i * 65536;
        int tsr = f4 / 524288;
        int off = (f4 - tsr * 524288) << 2;
        const float* s = (tsr == 0) ? inQ : (tsr == 1) ? inK : inV;
        float4 v = *(const float4*)(s + off);
        uint2 u = { pack_f16x2(v.x, v.y), pack_f16x2(v.z, v.w) };
        *(uint2*)(g_inh + (size_t)tsr*BB*SS*DD + off) = u;
    }
}

// ---------------------------------------------------------------------------
// fp16 GEMM v1 (qkv): K-chunk 32, 4-stage, BM=64 BN=128. [R13 measured winner]
// ---------------------------------------------------------------------------
#define GSTR 40

template<int BM, int BN, int EPI>
__device__ __forceinline__ void gemm_f16(const __half* __restrict__ Ag,
                                         const __half* __restrict__ Wg,
                                         const float* __restrict__ bg,
                                         float* __restrict__ Cg,
                                         int bm, int bn_local, int z) {
    extern __shared__ __half sh[];
    constexpr int SS_A  = BM * GSTR;
    constexpr int SS_B  = BN * GSTR;
    constexpr int SS_AB = SS_A + SS_B;
    constexpr int NWM = 8 / (BN / 32);
    constexpr int TM  = BM / (NWM * 16);
    float* bias_s = (float*)(sh + 4 * SS_AB);
    const uint32_t sb = smem_u32(sh);
    const int tid = threadIdx.x;
    const int wid = tid >> 5, lane = tid & 31, gid = lane >> 2, tig = lane & 3;
    const int warp_m = wid % NWM, warp_n = wid / NWM;
    const int lrow = lane & 15, lcol = (lane >> 4) << 3;

    if (tid < BN) bias_s[tid] = bg[tid];

    float acc[TM][4][4];
#pragma unroll
    for (int a = 0; a < TM; a++)
#pragma unroll
        for (int b = 0; b < 4; b++)
#pragma unroll
            for (int k = 0; k < 4; k++) acc[a][b][k] = 0.f;

    const int r0 = tid >> 2, c0 = (tid & 3) << 3;
    const __half* pA = Ag + (size_t)(bm + r0) * DD + c0;
    const __half* pB = Wg + (size_t)(bn_local + r0) * DD + c0;

#define G_LOAD(cc, buf) do { \
    _Pragma("unroll") \
    for (int i = 0; i < BM/64; i++) \
        cpa16(sb + (uint32_t)((buf)*SS_AB + (i*64 + r0)*GSTR + c0)*2, \
              pA + (size_t)i*64*DD + (cc)*32); \
    _Pragma("unroll") \
    for (int i = 0; i < BN/64; i++) \
        cpa16(sb + (uint32_t)((buf)*SS_AB + SS_A + (i*64 + r0)*GSTR + c0)*2, \
              pB + (size_t)i*64*DD + (cc)*32); \
    cpa_commit(); \
} while (0)

    G_LOAD(0, 0); G_LOAD(1, 1); G_LOAD(2, 2);

    for (int c = 0; c < 16; c++) {
        asm volatile("cp.async.wait_group 2;");
        __syncthreads();
        if (c + 3 < 16) G_LOAD(c + 3, (c + 3) & 3); else cpa_commit();

        const uint32_t abase = sb + (uint32_t)((c & 3) * SS_AB) * 2;
        const uint32_t bbase = abase + (uint32_t)SS_A * 2;
#pragma unroll
        for (int ks = 0; ks < 2; ks++) {
            uint32_t af[TM][4];
#pragma unroll
            for (int mt = 0; mt < TM; mt++)
                ldm_x4(af[mt][0], af[mt][1], af[mt][2], af[mt][3],
                       abase + (uint32_t)((warp_m*(BM/NWM) + mt*16 + lrow)*GSTR + ks*16 + lcol)*2);
#pragma unroll
            for (int ns = 0; ns < 2; ns++) {
                uint32_t b0, b1, b2, b3;
                ldm_x4(b0, b1, b2, b3,
                       bbase + (uint32_t)((warp_n*32 + ns*16 + lrow)*GSTR + ks*16 + lcol)*2);
#pragma unroll
                for (int mt = 0; mt < TM; mt++) {
                    mma_f16(acc[mt][ns*2],   af[mt], b0, b2);
                    mma_f16(acc[mt][ns*2+1], af[mt], b1, b3);
                }
            }
        }
    }
#undef G_LOAD

#pragma unroll
    for (int mt = 0; mt < TM; mt++) {
        int rg = bm + warp_m*(BM/NWM) + mt*16 + gid;
#pragma unroll
        for (int tn = 0; tn < 4; tn++) {
            int cc = warp_n*32 + tn*8 + tig*2;
            float b0 = bias_s[cc], b1 = bias_s[cc+1];
            if (EPI == 0) {
                *(float2*)(Cg + (size_t)rg*DD + bn_local + cc) =
                    make_float2(acc[mt][tn][0] + b0, acc[mt][tn][1] + b1);
                *(float2*)(Cg + (size_t)(rg+8)*DD + bn_local + cc) =
                    make_float2(acc[mt][tn][2] + b0, acc[mt][tn][3] + b1);
            } else {
                int col = bn_local + cc;
                int h = col >> 6, d = col & 63;
#pragma unroll
                for (int rr = 0; rr < 2; rr++) {
                    int rgl = rg + rr*8;
                    int b = rgl >> 11, s = rgl & 2047;
                    uint32_t hv = pack_f16x2(acc[mt][tn][rr*2+0] + b0,
                                             acc[mt][tn][rr*2+1] + b1);
                    *(uint32_t*)(g_h16 + ((((size_t)z*BB + b)*HH + h)*SS + s)*DKK + d) = hv;
                }
            }
        }
    }
}

#define GEMM_SMEM_QKV (4*((64 + 128)*GSTR)*2 + 512)

__global__ void __launch_bounds__(256, 3) qkv_tc_kernel() {
    int bm = blockIdx.x * 64;
    int b = bm >> 11, s_start = bm & 2047;
    int need = max(g_len[b], g_len[BB + b]);
    need = (need + 63) & ~63;
    if (s_start >= need) return;
    int bn = blockIdx.y * 128;
    int z = bn >> 9;
    gemm_f16<64, 128, 1>(g_inh + (size_t)z*BB*SS*DD, g_Wh + (size_t)z*DD*DD,
                         g_bqkv + bn, nullptr, bm, bn & 511, z);
}

// ---------------------------------------------------------------------------
// fp16 GEMM v2 (oproj): K-chunk 64, 3-stage, BM=64 BN=128. [R15 measured]
// ---------------------------------------------------------------------------
#define OSTR 72
#define OPROJ_STAGE ((64 + 128) * OSTR)
#define GEMM_SMEM_OPROJ (3 * OPROJ_STAGE * 2 + 512)

__global__ void __launch_bounds__(256, 2) oproj_tc_kernel(const float* __restrict__ bO,
                                                          float* __restrict__ out) {
    int bm = blockIdx.x * 64;
    int b = bm >> 11, s_start = bm & 2047;
    int rl = g_len[b];
    int bn = blockIdx.y * 128;
    const float* bg = bO + bn;
    if (s_start >= rl) {
#pragma unroll
        for (int i = 0; i < 8; i++) {
            int idx = threadIdx.x + i*256;
            int r = idx >> 5, cf = (idx & 31) << 2;
            float4 bv = *(const float4*)(bg + cf);
            *(float4*)(out + (size_t)(bm + r)*DD + bn + cf) = bv;
        }
        return;
    }

    extern __shared__ __half sh[];
    constexpr int SS_A = 64 * OSTR;
    float* bias_s = (float*)(sh + 3 * OPROJ_STAGE);
    const uint32_t sb = smem_u32(sh);
    const int tid = threadIdx.x;
    const int wid = tid >> 5, lane = tid & 31, gid = lane >> 2, tig = lane & 3;
    const int warp_m = wid & 1, warp_n = wid >> 1;
    const int lrow = lane & 15, lcol = (lane >> 4) << 3;

    if (tid < 128) bias_s[tid] = bg[tid];

    float acc[2][4][4];
#pragma unroll
    for (int a = 0; a < 2; a++)
#pragma unroll
        for (int bq = 0; bq < 4; bq++)
#pragma unroll
            for (int k = 0; k < 4; k++) acc[a][bq][k] = 0.f;

    const int r0 = tid >> 3, c0 = (tid & 7) << 3;
    const __half* pA = g_Hc16 + (size_t)(bm + r0) * DD + c0;
    const __half* pB = g_Wh + 3*(size_t)DD*DD + (size_t)(bn + r0) * DD + c0;

#define O_LOAD(cc, buf) do { \
    _Pragma("unroll") \
    for (int i = 0; i < 2; i++) \
        cpa16(sb + (uint32_t)((buf)*OPROJ_STAGE + (i*32 + r0)*OSTR + c0)*2, \
              pA + (size_t)i*32*DD + (cc)*64); \
    _Pragma("unroll") \
    for (int i = 0; i < 4; i++) \
        cpa16(sb + (uint32_t)((buf)*OPROJ_STAGE + SS_A + (i*32 + r0)*OSTR + c0)*2, \
              pB + (size_t)i*32*DD + (cc)*64); \
    cpa_commit(); \
} while (0)

    O_LOAD(0, 0); O_LOAD(1, 1);

    for (int c = 0; c < 8; c++) {
        asm volatile("cp.async.wait_group 1;");
        __syncthreads();
        if (c + 2 < 8) O_LOAD(c + 2, (c + 2) % 3); else cpa_commit();

        const uint32_t abase = sb + (uint32_t)((c % 3) * OPROJ_STAGE) * 2;
        const uint32_t bbase = abase + (uint32_t)SS_A * 2;
#pragma unroll
        for (int ks = 0; ks < 4; ks++) {
            uint32_t af[2][4];
#pragma unroll
            for (int mt = 0; mt < 2; mt++)
                ldm_x4(af[mt][0], af[mt][1], af[mt][2], af[mt][3],
                       abase + (uint32_t)((warp_m*32 + mt*16 + lrow)*OSTR + ks*16 + lcol)*2);
#pragma unroll
            for (int ns = 0; ns < 2; ns++) {
                uint32_t b0, b1, b2, b3;
                ldm_x4(b0, b1, b2, b3,
                       bbase + (uint32_t)((warp_n*32 + ns*16 + lrow)*OSTR + ks*16 + lcol)*2);
#pragma unroll
                for (int mt = 0; mt < 2; mt++) {
                    mma_f16(acc[mt][ns*2],   af[mt], b0, b2);
                    mma_f16(acc[mt][ns*2+1], af[mt], b1, b3);
                }
            }
        }
    }
#undef O_LOAD

#pragma unroll
    for (int mt = 0; mt < 2; mt++) {
        int rg = bm + warp_m*32 + mt*16 + gid;
#pragma unroll
        for (int tn = 0; tn < 4; tn++) {
            int cc = warp_n*32 + tn*8 + tig*2;
            float b0 = bias_s[cc], b1 = bias_s[cc+1];
            *(float2*)(out + (size_t)rg*DD + bn + cc) =
                make_float2(acc[mt][tn][0] + b0, acc[mt][tn][1] + b1);
            *(float2*)(out + (size_t)(rg+8)*DD + bn + cc) =
                make_float2(acc[mt][tn][2] + b0, acc[mt][tn][3] + b1);
        }
    }
}

// ---------------------------------------------------------------------------
// Flash attention (fp16 fragments), Br=64 x Bc=128, 128 threads (4 warps).
// Dense tiles (fully unrolled inner loops); tile-level nk bound only.
// Dead q-tiles return without zero-fill (oproj bias path covers those rows).
// smem halfs (stride 72): Q[64][72]@0  K[2][128][72]@4608  V[2][128][72]@23040
// ---------------------------------------------------------------------------
#define HSTR 72
#define AQ 0
#define AK 4608
#define AV 23040
#define ATTN_SMEM (41472*2)

__global__ void __launch_bounds__(128, 2) attn_kernel() {
    extern __shared__ __half sah[];
    const uint32_t sb = smem_u32(sah);

    const int bh = blockIdx.z;
    const int b = bh >> 3, h = bh & 7;
    const int qt = 31 - (int)blockIdx.y;      // heavy tiles first
    const int qbase = qt << 6;
    const int rowlen = g_len[b], collen = g_len[BB + b];
    const int tid = threadIdx.x, wid = tid >> 5, lane = tid & 31;
    const int gid = lane >> 2, tig = lane & 3;
    __half* Hp = g_Hc16 + (size_t)b*SS*DD + h*DKK;

    if (qbase >= rowlen || collen <= 0) return;   // oproj bias path covers these rows

    const __half* Qp = g_h16 + ((0*(size_t)BB + b)*HH + h)*(size_t)SS*DKK;
    const __half* Kp = g_h16 + ((1*(size_t)BB + b)*HH + h)*(size_t)SS*DKK;
    const __half* Vp = g_h16 + ((2*(size_t)BB + b)*HH + h)*(size_t)SS*DKK;

    const int kmax = min(qbase + 64, collen);
    const int nk = (kmax + 127) >> 7;          // 128-wide k-tiles

#pragma unroll
    for (int i = 0; i < 4; i++) {
        int e = tid + i*128, r = e >> 3, c8 = (e & 7) << 3;
        cpa16(sb + (uint32_t)(AQ + r*HSTR + c8)*2, Qp + (size_t)(qbase + r)*DKK + c8);
    }
#define KV_LOAD(kb, s) do { \
    _Pragma("unroll") \
    for (int i = 0; i < 8; i++) { \
        int e = tid + i*128, r = e >> 3, c8 = (e & 7) << 3; \
        cpa16(sb + (uint32_t)(AK + (s)*9216 + r*HSTR + c8)*2, Kp + (size_t)((kb) + r)*DKK + c8); \
        cpa16(sb + (uint32_t)(AV + (s)*9216 + r*HSTR + c8)*2, Vp + (size_t)((kb) + r)*DKK + c8); \
    } \
} while (0)
    KV_LOAD(0, 0); cpa_commit();

    const int wr = wid * 16;
    const int q0 = qbase + wr + gid, q1 = q0 + 8;
    float m0 = -1e30f, m1 = -1e30f, l0 = 0.f, l1 = 0.f;
    float oacc[8][4];
#pragma unroll
    for (int nt = 0; nt < 8; nt++)
#pragma unroll
        for (int i = 0; i < 4; i++) oacc[nt][i] = 0.f;

    uint32_t qf[4][4];
    const int lrow = lane & 15, lcol = (lane >> 4) << 3;

    for (int kt = 0; kt < nk; kt++) {
        const int kbase = kt << 7;
        const int buf = kt & 1;
        asm volatile("cp.async.wait_group 0;");
        __syncthreads();
        if (kt == 0) {
#pragma unroll
            for (int ks = 0; ks < 4; ks++)
                ldm_x4(qf[ks][0], qf[ks][1], qf[ks][2], qf[ks][3],
                       sb + (uint32_t)(AQ + (wr + lrow)*HSTR + ks*16 + lcol)*2);
        }
        if (kt + 1 < nk) { KV_LOAD(kbase + 128, buf ^ 1); cpa_commit(); }

        const uint32_t kbuf = sb + (uint32_t)(AK + buf*9216)*2;
        const uint32_t vbuf = sb + (uint32_t)(AV + buf*9216)*2;

        float sacc[16][4];
#pragma unroll
        for (int nt = 0; nt < 16; nt++)
#pragma unroll
            for (int i = 0; i < 4; i++) sacc[nt][i] = 0.f;
#pragma unroll
        for (int ks = 0; ks < 4; ks++) {
#pragma unroll
            for (int nb = 0; nb < 8; nb++) {
                uint32_t r0, r1, r2, r3;
                ldm_x4(r0, r1, r2, r3,
                       kbuf + (uint32_t)((nb*16 + lrow)*HSTR + ks*16 + lcol)*2);
                mma_f16(sacc[nb*2],   qf[ks], r0, r2);
                mma_f16(sacc[nb*2+1], qf[ks], r1, r3);
            }
        }

#pragma unroll
        for (int nt = 0; nt < 16; nt++) {
            const int kc = kbase + nt*8 + tig*2;
            sacc[nt][0] = (kc   <= q0 && q0 < rowlen && kc   < collen) ? sacc[nt][0]*0.125f : -1e30f;
            sacc[nt][1] = (kc+1 <= q0 && q0 < rowlen && kc+1 < collen) ? sacc[nt][1]*0.125f : -1e30f;
            sacc[nt][2] = (kc   <= q1 && q1 < rowlen && kc   < collen) ? sacc[nt][2]*0.125f : -1e30f;
            sacc[nt][3] = (kc+1 <= q1 && q1 < rowlen && kc+1 < collen) ? sacc[nt][3]*0.125f : -1e30f;
        }

        float a0 = -1e30f, a1 = -1e30f;
#pragma unroll
        for (int nt = 0; nt < 16; nt++) {
            a0 = fmaxf(a0, fmaxf(sacc[nt][0], sacc[nt][1]));
            a1 = fmaxf(a1, fmaxf(sacc[nt][2], sacc[nt][3]));
        }
        a0 = fmaxf(a0, __shfl_xor_sync(0xffffffffu, a0, 1));
        a0 = fmaxf(a0, __shfl_xor_sync(0xffffffffu, a0, 2));
        a1 = fmaxf(a1, __shfl_xor_sync(0xffffffffu, a1, 1));
        a1 = fmaxf(a1, __shfl_xor_sync(0xffffffffu, a1, 2));

        const float mn0 = fmaxf(m0, a0), mn1 = fmaxf(m1, a1);
        const float sc0 = __expf(m0 - mn0), sc1 = __expf(m1 - mn1);
        l0 *= sc0; l1 *= sc1; m0 = mn0; m1 = mn1;
#pragma unroll
        for (int nt = 0; nt < 8; nt++) {
            oacc[nt][0] *= sc0; oacc[nt][1] *= sc0;
            oacc[nt][2] *= sc1; oacc[nt][3] *= sc1;
        }

        float rs0 = 0.f, rs1 = 0.f;
#pragma unroll
        for (int nt = 0; nt < 16; nt++) {
            sacc[nt][0] = __expf(sacc[nt][0] - mn0);
            sacc[nt][1] = __expf(sacc[nt][1] - mn0);
            sacc[nt][2] = __expf(sacc[nt][2] - mn1);
            sacc[nt][3] = __expf(sacc[nt][3] - mn1);
            rs0 += sacc[nt][0] + sacc[nt][1];
            rs1 += sacc[nt][2] + sacc[nt][3];
        }
        rs0 += __shfl_xor_sync(0xffffffffu, rs0, 1);
        rs0 += __shfl_xor_sync(0xffffffffu, rs0, 2);
        rs1 += __shfl_xor_sync(0xffffffffu, rs1, 1);
        rs1 += __shfl_xor_sync(0xffffffffu, rs1, 2);
        l0 += rs0; l1 += rs1;

#pragma unroll
        for (int ks = 0; ks < 8; ks++) {
            uint32_t pa[4];
            pa[0] = pack_f16x2(sacc[2*ks][0],   sacc[2*ks][1]);
            pa[1] = pack_f16x2(sacc[2*ks][2],   sacc[2*ks][3]);
            pa[2] = pack_f16x2(sacc[2*ks+1][0], sacc[2*ks+1][1]);
            pa[3] = pack_f16x2(sacc[2*ks+1][2], sacc[2*ks+1][3]);
#pragma unroll
            for (int db = 0; db < 4; db++) {
                uint32_t v0, v1, v2, v3;
                ldm_x4_t(v0, v1, v2, v3,
                         vbuf + (uint32_t)((ks*16 + lrow)*HSTR + db*16 + lcol)*2);
                mma_f16(oacc[db*2],   pa, v0, v1);
                mma_f16(oacc[db*2+1], pa, v2, v3);
            }
        }
    }
#undef KV_LOAD

    const float inv0 = (q0 < rowlen && l0 > 0.f) ? 1.f / l0 : 0.f;
    const float inv1 = (q1 < rowlen && l1 > 0.f) ? 1.f / l1 : 0.f;
#pragma unroll
    for (int nt = 0; nt < 8; nt++) {
        const int cc = nt*8 + tig*2;
        *(uint32_t*)(Hp + (size_t)q0*DD + cc) = pack_f16x2(oacc[nt][0]*inv0, oacc[nt][1]*inv0);
        *(uint32_t*)(Hp + (size_t)q1*DD + cc) = pack_f16x2(oacc[nt][2]*inv1, oacc[nt][3]*inv1);
    }
}

// ---------------------------------------------------------------------------
extern "C" void kernel_launch(void* const* d_in, const int* in_sizes, int n_in,
                              void* d_out, int out_size) {
    const float* in_Q = (const float*)d_in[0];
    const float* in_K = (const float*)d_in[1];
    const float* in_V = (const float*)d_in[2];
    const int*   rm   = (const int*)d_in[3];
    const int*   cm   = (const int*)d_in[4];
    const float* WQ = (const float*)d_in[5];  const float* bQ = (const float*)d_in[6];
    const float* WK = (const float*)d_in[7];  const float* bK = (const float*)d_in[8];
    const float* WV = (const float*)d_in[9];  const float* bV = (const float*)d_in[10];
    const float* WO = (const float*)d_in[11]; const float* bO = (const float*)d_in[12];
    float* out = (float*)d_out;

    cudaFuncSetAttribute(qkv_tc_kernel,   cudaFuncAttributeMaxDynamicSharedMemorySize, GEMM_SMEM_QKV);
    cudaFuncSetAttribute(oproj_tc_kernel, cudaFuncAttributeMaxDynamicSharedMemorySize, GEMM_SMEM_OPROJ);
    cudaFuncSetAttribute(attn_kernel,     cudaFuncAttributeMaxDynamicSharedMemorySize, ATTN_SMEM);

    prep_kernel<<<322, 256>>>(rm, cm, WQ, WK, WV, WO, bQ, bK, bV, in_Q, in_K, in_V);

    dim3 g1(64, 12);                   // M=4096/64, N=1536/128
    qkv_tc_kernel<<<g1, 256, GEMM_SMEM_QKV>>>();

    dim3 g2(1, 32, 16);                // 64-row q-tiles x (b*h), heavy-first
    attn_kernel<<<g2, 128, ATTN_SMEM>>>();

    dim3 g3(64, 4);                    // M=4096/64, N=512/128
    oproj_tc_kernel<<<g3, 256, GEMM_SMEM_OPROJ>>>(bO, out);
}